// round 8
// baseline (speedup 1.0000x reference)
#include <cuda_runtime.h>
#include <cuda_fp16.h>
#include <cstdint>
#include <cstddef>

#define B_ 16
#define L_ 16384
#define C_ 256
#define NH 8
#define FFN 512
#define EPS 1e-5f
#define SCALE_ATT 0.17677669529663687f
#define JOBS 4096

// k1 smem byte offsets (97152 total -> occupancy 2)
#define O_A   0         /* A fp16 chunk: 64 x 40 halves = 5120 */
#define O_B0  5120      /* B fp16 double buffer: 2 x 20480 */
#define O_MSM 0         /* m^ fp16 [64][264] = 33792, overlays GEMM bufs */
#define O_SPC 46080     /* score partials (8KB) then ctx partials (32KB) */
#define O_GQ  78848     /* gq fp32 [8][264] = 8448 */
#define O_IOR 87296     /* 8*64 */
#define O_WSM 89344     /* 8*64 */
#define O_ST  91392     /* 64*4 sums + 64*4 sumsq */
#define O_MU  93440
#define O_RS  93696
#define O_CG  93952
#define O_CQC 93984
#define O_CS2 94016
#define O_CW  94048
#define O_BIP 94080
#define O_GIP 95104
#define O_BEI 96128
#define SM1   97152

__device__ float g_gq[B_ * NH * C_];
__device__ float g_G[B_ * NH];
__device__ float g_qc[B_ * NH];
__device__ float g_pmax[JOBS * NH];
__device__ float g_psum[JOBS * NH];
__device__ float g_pctx[(size_t)JOBS * NH * C_];
__device__ float g_ctxn[B_ * NH * C_];
__device__ __align__(16) __half g_wh[C_ * C_];   // W_ip^T fp16, n-major

__device__ __forceinline__ uint32_t smem_u32(const void* p) {
    uint32_t a;
    asm("{ .reg .u64 t; cvta.to.shared.u64 t, %1; cvt.u32.u64 %0, t; }" : "=r"(a) : "l"(p));
    return a;
}
__device__ __forceinline__ void ldmx4(uint32_t* r, uint32_t a) {
    asm volatile("ldmatrix.sync.aligned.m8n8.x4.shared.b16 {%0,%1,%2,%3}, [%4];"
        : "=r"(r[0]), "=r"(r[1]), "=r"(r[2]), "=r"(r[3]) : "r"(a));
}
__device__ __forceinline__ void mma16816(float* d, const uint32_t* a, uint32_t b0, uint32_t b1) {
    asm volatile("mma.sync.aligned.m16n8k16.row.col.f32.f16.f16.f32 "
        "{%0,%1,%2,%3}, {%4,%5,%6,%7}, {%8,%9}, {%0,%1,%2,%3};"
        : "+f"(d[0]), "+f"(d[1]), "+f"(d[2]), "+f"(d[3])
        : "r"(a[0]), "r"(a[1]), "r"(a[2]), "r"(a[3]), "r"(b0), "r"(b1));
}
#define CPA(dst, src) asm volatile("cp.async.cg.shared.global [%0], [%1], 16;" :: "r"(dst), "l"(src))
#define CPC() asm volatile("cp.async.commit_group;" ::: "memory")
#define CPW(n) asm volatile("cp.async.wait_group %0;" :: "n"(n) : "memory")

// ---- K0b: W_ip^T -> fp16, n-major ----
__global__ void k0b(const float* __restrict__ W_ip) {
    const int n = blockIdx.x, k = threadIdx.x;
    g_wh[n * C_ + k] = __float2half_rn(W_ip[k * C_ + n]);
}

// ---- K0: fold LN(query)@W_q into gq/G/QC ----
__global__ void k0(const float* __restrict__ query, const float* __restrict__ W_q,
                   const float* __restrict__ b_q, const float* __restrict__ W_kv,
                   const float* __restrict__ b_kv, const float* __restrict__ g_q,
                   const float* __restrict__ be_q, const float* __restrict__ g_ip,
                   const float* __restrict__ be_ip) {
    __shared__ float qn[C_], qs[C_], red[8], red2[8], sG[NH], sQ[NH];
    const int b = blockIdx.x, t = threadIdx.x;
    float x = query[b * C_ + t];
    float s = x, s2 = x * x;
    #pragma unroll
    for (int o = 16; o >= 1; o >>= 1) {
        s += __shfl_xor_sync(~0u, s, o);
        s2 += __shfl_xor_sync(~0u, s2, o);
    }
    if ((t & 31) == 0) { red[t >> 5] = s; red2[t >> 5] = s2; }
    __syncthreads();
    float su = 0.f, sq = 0.f;
    #pragma unroll
    for (int i = 0; i < 8; i++) { su += red[i]; sq += red2[i]; }
    float mean = su / C_, var = sq / C_ - mean * mean, rs = rsqrtf(var + EPS);
    qn[t] = (x - mean) * rs * g_q[t] + be_q[t];
    __syncthreads();
    float a0 = 0.f, a1 = 0.f, a2 = 0.f, a3 = 0.f;
    #pragma unroll 8
    for (int c = 0; c < C_; c += 4) {
        a0 += qn[c] * W_q[c * C_ + t];
        a1 += qn[c + 1] * W_q[(c + 1) * C_ + t];
        a2 += qn[c + 2] * W_q[(c + 2) * C_ + t];
        a3 += qn[c + 3] * W_q[(c + 3) * C_ + t];
    }
    qs[t] = b_q[t] + (a0 + a1) + (a2 + a3);
    __syncthreads();
    const float* wr = W_kv + (size_t)t * (2 * C_);
    const float gI = g_ip[t], bE = be_ip[t];
    for (int h = 0; h < NH; h++) {
        float acc = 0.f;
        #pragma unroll 8
        for (int d = 0; d < 32; d++) acc += qs[h * 32 + d] * wr[h * 32 + d];
        acc *= SCALE_ATT;
        g_gq[(b * NH + h) * C_ + t] = acc * gI;
        float r1v = acc * gI, r2v = acc * bE;
        #pragma unroll
        for (int o = 16; o >= 1; o >>= 1) {
            r1v += __shfl_xor_sync(~0u, r1v, o);
            r2v += __shfl_xor_sync(~0u, r2v, o);
        }
        if ((t & 31) == 0) { red[t >> 5] = r1v; red2[t >> 5] = r2v; }
        __syncthreads();
        if (t == 0) {
            float gsum = 0.f, qsum = 0.f;
            #pragma unroll
            for (int i = 0; i < 8; i++) { gsum += red[i]; qsum += red2[i]; }
            sG[h] = gsum; sQ[h] = qsum;
        }
        __syncthreads();
    }
    if (t < NH) {
        float qb = 0.f;
        #pragma unroll 8
        for (int d = 0; d < 32; d++) qb += qs[t * 32 + d] * b_kv[t * 32 + d];
        g_G[b * NH + t] = sG[t];
        g_qc[b * NH + t] = sQ[t] + qb * SCALE_ATT;
    }
}

// ---- K1: fp16 HMMA fused kernel, 64-row tiles, occupancy 2 ----
__global__ void __launch_bounds__(512, 2)
k1(const float* __restrict__ mem, const float* __restrict__ ior,
   const float* __restrict__ b_ip, const float* __restrict__ g_ip,
   const float* __restrict__ be_ip) {
    extern __shared__ char sm[];
    float* S = (float*)sm;
    const uint32_t smb = smem_u32(sm);
    const int t = threadIdx.x, lane = t & 31, wid = t >> 5;
    const int rg = wid >> 2, cg = wid & 3;   // 4 row groups x 4 col groups
    const int j = blockIdx.x, b = j >> 8, row0 = (j & 255) << 6;

    // per-block init
    for (int i = t; i < NH * C_; i += 512)
        S[(O_GQ >> 2) + (i >> 8) * 264 + (i & 255)] = g_gq[b * NH * C_ + i];
    if (t < NH) {
        S[(O_CG >> 2) + t] = g_G[b * NH + t];
        S[(O_CQC >> 2) + t] = g_qc[b * NH + t];
    }
    if (t < NH * 64)
        S[(O_IOR >> 2) + t] = ior[(size_t)(b * NH + (t >> 6)) * L_ + row0 + (t & 63)];
    if (t < C_) {
        S[(O_BIP >> 2) + t] = b_ip[t];
        S[(O_GIP >> 2) + t] = g_ip[t];
        S[(O_BEI >> 2) + t] = be_ip[t];
    }

    // ---- GEMM: [64,256] = A[64,256] @ B^T, fp16, K-chunks of 32 ----
    const float4* mem4 = (const float4*)mem;
    const int ar = t >> 3, aq = t & 7;
    const size_t abase = (size_t)(b * L_ + row0 + ar) * 64;
    float4 av = mem4[abase + aq];

    const int bn = t >> 1, bf = t & 1;
    {
        const char* sH = (const char*)g_wh + ((size_t)bn * 256 + bf * 16) * 2;
        uint32_t d0 = smb + O_B0 + bn * 80 + bf * 32;
        CPA(d0, sH); CPA(d0 + 16, sH + 16);
        CPC();
    }

    float d[8][4];
    #pragma unroll
    for (int i = 0; i < 8; i++)
        #pragma unroll
        for (int q = 0; q < 4; q++) d[i][q] = 0.f;

    const int lg = lane >> 3, lr = lane & 7;
    const uint32_t aAddr = smb + O_A + (rg * 16 + ((lg & 1) << 3) + lr) * 80 + (lg >> 1) * 16;
    const uint32_t bOff = (cg * 64 + ((lg >> 1) << 3) + lr) * 80 + (lg & 1) * 16;

    for (int kc = 0; kc < 8; kc++) {
        __syncthreads();
        {   // A regs -> smem fp16 (8 bytes/thread)
            __half2 h0 = __floats2half2_rn(av.x, av.y);
            __half2 h1 = __floats2half2_rn(av.z, av.w);
            *(uint2*)(sm + O_A + ar * 80 + aq * 8) =
                make_uint2(*(uint32_t*)&h0, *(uint32_t*)&h1);
        }
        if (kc < 7) {
            av = mem4[abase + (kc + 1) * 8 + aq];
            const char* sH = (const char*)g_wh + ((size_t)bn * 256 + (kc + 1) * 32 + bf * 16) * 2;
            uint32_t d0 = smb + O_B0 + ((kc + 1) & 1) * 20480 + bn * 80 + bf * 32;
            CPA(d0, sH); CPA(d0 + 16, sH + 16);
            CPC();
            CPW(1);
        } else {
            CPW(0);
        }
        __syncthreads();

        uint32_t bufB = smb + O_B0 + (kc & 1) * 20480 + bOff;
        #pragma unroll
        for (int ks = 0; ks < 2; ks++) {
            uint32_t ah[4];
            ldmx4(ah, aAddr + ks * 32);
            uint32_t bh[4][4];
            #pragma unroll
            for (int jt = 0; jt < 4; jt++)
                ldmx4(bh[jt], bufB + jt * 1280 + ks * 32);
            #pragma unroll
            for (int jt = 0; jt < 4; jt++) {
                mma16816(d[2 * jt], ah, bh[jt][0], bh[jt][1]);
                mma16816(d[2 * jt + 1], ah, bh[jt][2], bh[jt][3]);
            }
        }
    }
    __syncthreads();   // ldmatrix reads done; msm may overwrite GEMM bufs

    // ---- pass 1: bias+relu, stats, msm write, score partials ----
    const int r0 = rg * 16 + (lane >> 2), r1 = r0 + 8;
    const int cq = (lane & 3) * 2;
    float s0 = 0.f, q0 = 0.f, s1 = 0.f, q1 = 0.f;
    float p0[NH], p1[NH];
    #pragma unroll
    for (int h = 0; h < NH; h++) { p0[h] = 0.f; p1[h] = 0.f; }
    #pragma unroll
    for (int nt = 0; nt < 8; nt++) {
        int c = cg * 64 + nt * 8 + cq;
        float2 bb = *(float2*)&S[(O_BIP >> 2) + c];
        float x0 = fmaxf(d[nt][0] + bb.x, 0.f), x1 = fmaxf(d[nt][1] + bb.y, 0.f);
        float y0 = fmaxf(d[nt][2] + bb.x, 0.f), y1 = fmaxf(d[nt][3] + bb.y, 0.f);
        s0 += x0 + x1; q0 += x0 * x0 + x1 * x1;
        s1 += y0 + y1; q1 += y0 * y0 + y1 * y1;
        *(__half2*)(sm + O_MSM + (r0 * 264 + c) * 2) = __floats2half2_rn(x0, x1);
        *(__half2*)(sm + O_MSM + (r1 * 264 + c) * 2) = __floats2half2_rn(y0, y1);
        #pragma unroll
        for (int h = 0; h < NH; h++) {
            float2 qv = *(float2*)&S[(O_GQ >> 2) + h * 264 + c];
            p0[h] += x0 * qv.x + x1 * qv.y;
            p1[h] += y0 * qv.x + y1 * qv.y;
        }
    }
    #pragma unroll
    for (int o = 1; o <= 2; o <<= 1) {
        s0 += __shfl_xor_sync(~0u, s0, o); q0 += __shfl_xor_sync(~0u, q0, o);
        s1 += __shfl_xor_sync(~0u, s1, o); q1 += __shfl_xor_sync(~0u, q1, o);
        #pragma unroll
        for (int h = 0; h < NH; h++) {
            p0[h] += __shfl_xor_sync(~0u, p0[h], o);
            p1[h] += __shfl_xor_sync(~0u, p1[h], o);
        }
    }
    if ((lane & 3) == 0) {
        S[(O_ST >> 2) + r0 * 4 + cg] = s0; S[(O_ST >> 2) + 256 + r0 * 4 + cg] = q0;
        S[(O_ST >> 2) + r1 * 4 + cg] = s1; S[(O_ST >> 2) + 256 + r1 * 4 + cg] = q1;
        #pragma unroll
        for (int h = 0; h < NH; h++) {
            S[(O_SPC >> 2) + (r0 * 8 + h) * 4 + cg] = p0[h];
            S[(O_SPC >> 2) + (r1 * 8 + h) * 4 + cg] = p1[h];
        }
    }
    __syncthreads();

    // ---- score combine: sc = (rs*(P - mu*G) + QC) * ior ----
    {
        int h = t >> 6, rr = t & 63;
        const float* sp = S + (O_SPC >> 2) + (rr * 8 + h) * 4;
        float P = (sp[0] + sp[1]) + (sp[2] + sp[3]);
        const float* st = S + (O_ST >> 2) + rr * 4;
        float su2 = (st[0] + st[1]) + (st[2] + st[3]);
        const float* st2 = S + (O_ST >> 2) + 256 + rr * 4;
        float sq2 = (st2[0] + st2[1]) + (st2[2] + st2[3]);
        float mu = su2 * (1.f / C_);
        float rs = rsqrtf(sq2 * (1.f / C_) - mu * mu + EPS);
        if (h == 0) { S[(O_MU >> 2) + rr] = mu; S[(O_RS >> 2) + rr] = rs; }
        S[(O_WSM >> 2) + t] = (rs * (P - mu * S[(O_CG >> 2) + h]) + S[(O_CQC >> 2) + h])
                              * S[(O_IOR >> 2) + t];
    }
    __syncthreads();

    // ---- per-tile softmax; WSM <- w*rs; W, s2 per head ----
    if (wid < NH) {
        float v0 = S[(O_WSM >> 2) + wid * 64 + lane];
        float v1 = S[(O_WSM >> 2) + wid * 64 + 32 + lane];
        float mx = fmaxf(v0, v1);
        #pragma unroll
        for (int o = 16; o >= 1; o >>= 1) mx = fmaxf(mx, __shfl_xor_sync(~0u, mx, o));
        float e0 = __expf(v0 - mx), e1 = __expf(v1 - mx);
        float rs0 = S[(O_RS >> 2) + lane],      mu0 = S[(O_MU >> 2) + lane];
        float rs1 = S[(O_RS >> 2) + 32 + lane], mu1 = S[(O_MU >> 2) + 32 + lane];
        S[(O_WSM >> 2) + wid * 64 + lane]      = e0 * rs0;
        S[(O_WSM >> 2) + wid * 64 + 32 + lane] = e1 * rs1;
        float es = e0 + e1;
        float s2 = e0 * rs0 * mu0 + e1 * rs1 * mu1;
        #pragma unroll
        for (int o = 16; o >= 1; o >>= 1) {
            es += __shfl_xor_sync(~0u, es, o);
            s2 += __shfl_xor_sync(~0u, s2, o);
        }
        if (lane == 0) {
            g_pmax[j * NH + wid] = mx;
            g_psum[j * NH + wid] = es;
            S[(O_CW >> 2) + wid] = es;
            S[(O_CS2 >> 2) + wid] = s2;
        }
    }
    __syncthreads();

    // ---- ctx partial: acc[h][c] = sum_r (w*rs) * m^ ----
    {
        const int cp = t & 127, sl = t >> 7;    // col-pair, 4 row slices of 16
        float2 a8[NH];
        #pragma unroll
        for (int h = 0; h < NH; h++) a8[h] = make_float2(0.f, 0.f);
        for (int r = sl * 16; r < sl * 16 + 16; r++) {
            uint32_t u = *(uint32_t*)(sm + O_MSM + r * 528 + cp * 4);
            float2 f = __half22float2(*(__half2*)&u);
            #pragma unroll
            for (int h = 0; h < NH; h++) {
                float w = S[(O_WSM >> 2) + h * 64 + r];
                a8[h].x += w * f.x; a8[h].y += w * f.y;
            }
        }
        #pragma unroll
        for (int h = 0; h < NH; h++)
            *(float2*)&S[(O_SPC >> 2) + (sl * 8 + h) * 256 + cp * 2] = a8[h];
        __syncthreads();
        // final reduce + LN-fold correction, write partial ctx
        const int hh = t >> 6, c4 = t & 63;     // head, float4 index
        float4 s4 = make_float4(0.f, 0.f, 0.f, 0.f);
        #pragma unroll
        for (int s2i = 0; s2i < 4; s2i++) {
            float4 v = *(float4*)&S[(O_SPC >> 2) + (s2i * 8 + hh) * 256 + c4 * 4];
            s4.x += v.x; s4.y += v.y; s4.z += v.z; s4.w += v.w;
        }
        float4 gg = *(float4*)&S[(O_GIP >> 2) + c4 * 4];
        float4 ee = *(float4*)&S[(O_BEI >> 2) + c4 * 4];
        float sh = S[(O_CS2 >> 2) + hh], Wh = S[(O_CW >> 2) + hh];
        float4 outv;
        outv.x = gg.x * (s4.x - sh) + ee.x * Wh;
        outv.y = gg.y * (s4.y - sh) + ee.y * Wh;
        outv.z = gg.z * (s4.z - sh) + ee.z * Wh;
        outv.w = gg.w * (s4.w - sh) + ee.w * Wh;
        ((float4*)g_pctx)[(size_t)j * 512 + hh * 64 + c4] = outv;
    }
}

// ---- K2a: parallel softmax-combine of 256 partials, one block per (b,h) ----
__global__ void k2a() {
    __shared__ float pm[256], ps[256], ef[256], red[8], red2[8], cacc[4 * 256];
    const int b = blockIdx.x >> 3, h = blockIdx.x & 7;
    const int t = threadIdx.x, lane = t & 31;
    const int col = t & 255, sl = t >> 8;
    if (t < 256) {
        pm[t] = g_pmax[(b * 256 + t) * NH + h];
        ps[t] = g_psum[(b * 256 + t) * NH + h];
    }
    __syncthreads();
    if (t < 256) {
        float v = pm[t];
        #pragma unroll
        for (int o = 16; o >= 1; o >>= 1) v = fmaxf(v, __shfl_xor_sync(~0u, v, o));
        if (lane == 0) red[t >> 5] = v;
    }
    __syncthreads();
    float gmax = red[0];
    #pragma unroll
    for (int i = 1; i < 8; i++) gmax = fmaxf(gmax, red[i]);
    if (t < 256) ef[t] = __expf(pm[t] - gmax);
    __syncthreads();
    if (t < 256) {
        float v = ps[t] * ef[t];
        #pragma unroll
        for (int o = 16; o >= 1; o >>= 1) v += __shfl_xor_sync(~0u, v, o);
        if (lane == 0) red2[t >> 5] = v;
    }
    __syncthreads();
    float acc = 0.f;
    const float* p = g_pctx + ((size_t)(b * 256 + sl * 64) * NH + h) * C_ + col;
    #pragma unroll 4
    for (int ch = 0; ch < 64; ch++)
        acc += ef[sl * 64 + ch] * p[(size_t)ch * NH * C_];
    cacc[sl * 256 + col] = acc;
    __syncthreads();
    if (sl == 0) {
        float den = 0.f;
        #pragma unroll
        for (int i = 0; i < 8; i++) den += red2[i];
        float tot = (cacc[col] + cacc[256 + col]) + (cacc[512 + col] + cacc[768 + col]);
        g_ctxn[(b * NH + h) * C_ + col] = tot / den;
    }
}

// ---- K2b: V-proj + residual + LN + FFN ----
__global__ void k2b(const float* __restrict__ query, const float* __restrict__ W_kv,
                    const float* __restrict__ b_kv, const float* __restrict__ g_f,
                    const float* __restrict__ be_f, const float* __restrict__ W1,
                    const float* __restrict__ b1, const float* __restrict__ W2,
                    const float* __restrict__ b2, float* __restrict__ out) {
    __shared__ float ctxn[NH * C_], xs[C_], hs[C_], us[FFN], red[8], red2[8];
    const int b = blockIdx.x, t = threadIdx.x;
    for (int i = t; i < NH * C_; i += 256) ctxn[i] = g_ctxn[b * NH * C_ + i];
    __syncthreads();
    {
        const int h = t >> 5;
        float a0 = 0.f, a1 = 0.f, a2 = 0.f, a3 = 0.f;
        #pragma unroll 8
        for (int c = 0; c < C_; c += 4) {
            a0 += ctxn[h * C_ + c] * W_kv[c * (2 * C_) + C_ + t];
            a1 += ctxn[h * C_ + c + 1] * W_kv[(c + 1) * (2 * C_) + C_ + t];
            a2 += ctxn[h * C_ + c + 2] * W_kv[(c + 2) * (2 * C_) + C_ + t];
            a3 += ctxn[h * C_ + c + 3] * W_kv[(c + 3) * (2 * C_) + C_ + t];
        }
        float x = b_kv[C_ + t] + (a0 + a1) + (a2 + a3) + query[b * C_ + t];
        xs[t] = x;
        float s = x, s2 = x * x;
        #pragma unroll
        for (int o = 16; o >= 1; o >>= 1) {
            s += __shfl_xor_sync(~0u, s, o);
            s2 += __shfl_xor_sync(~0u, s2, o);
        }
        if ((t & 31) == 0) { red[t >> 5] = s; red2[t >> 5] = s2; }
        __syncthreads();
        float su = 0.f, sq = 0.f;
        #pragma unroll
        for (int i = 0; i < 8; i++) { su += red[i]; sq += red2[i]; }
        float mean = su / C_, var = sq / C_ - mean * mean, rs = rsqrtf(var + EPS);
        hs[t] = (x - mean) * rs * g_f[t] + be_f[t];
    }
    __syncthreads();
    for (int f = t; f < FFN; f += 256) {
        float a0 = 0.f, a1 = 0.f, a2 = 0.f, a3 = 0.f;
        #pragma unroll 8
        for (int c = 0; c < C_; c += 4) {
            a0 += hs[c] * W1[c * FFN + f];
            a1 += hs[c + 1] * W1[(c + 1) * FFN + f];
            a2 += hs[c + 2] * W1[(c + 2) * FFN + f];
            a3 += hs[c + 3] * W1[(c + 3) * FFN + f];
        }
        float u = b1[f] + (a0 + a1) + (a2 + a3);
        us[f] = 0.5f * u * (1.f + erff(u * 0.70710678118654752f));
    }
    __syncthreads();
    {
        float a0 = 0.f, a1 = 0.f, a2 = 0.f, a3 = 0.f;
        #pragma unroll 8
        for (int f = 0; f < FFN; f += 4) {
            a0 += us[f] * W2[f * C_ + t];
            a1 += us[f + 1] * W2[(f + 1) * C_ + t];
            a2 += us[f + 2] * W2[(f + 2) * C_ + t];
            a3 += us[f + 3] * W2[(f + 3) * C_ + t];
        }
        out[b * C_ + t] = xs[t] + b2[t] + (a0 + a1) + (a2 + a3);
    }
}

extern "C" void kernel_launch(void* const* d_in, const int* in_sizes, int n_in,
                              void* d_out, int out_size) {
    const float* query = (const float*)d_in[0];
    const float* mem   = (const float*)d_in[1];
    const float* ior   = (const float*)d_in[2];
    const float* W_ip  = (const float*)d_in[3];
    const float* b_ip  = (const float*)d_in[4];
    const float* g_ip  = (const float*)d_in[5];
    const float* be_ip = (const float*)d_in[6];
    const float* W_q   = (const float*)d_in[7];
    const float* b_q   = (const float*)d_in[8];
    const float* W_kv  = (const float*)d_in[9];
    const float* b_kv  = (const float*)d_in[10];
    const float* g_q   = (const float*)d_in[11];
    const float* be_q  = (const float*)d_in[12];
    const float* g_f   = (const float*)d_in[13];
    const float* be_f  = (const float*)d_in[14];
    const float* W1    = (const float*)d_in[15];
    const float* b1    = (const float*)d_in[16];
    const float* W2    = (const float*)d_in[17];
    const float* b2    = (const float*)d_in[18];

    cudaFuncSetAttribute(k1, cudaFuncAttributeMaxDynamicSharedMemorySize, SM1);
    k0b<<<C_, C_>>>(W_ip);
    k0<<<B_, C_>>>(query, W_q, b_q, W_kv, b_kv, g_q, be_q, g_ip, be_ip);
    k1<<<JOBS, 512, SM1>>>(mem, ior, b_ip, g_ip, be_ip);
    k2a<<<B_ * NH, 1024>>>();
    k2b<<<B_, C_>>>(query, W_kv, b_kv, g_f, be_f, W1, b1, W2, b2, (float*)d_out);
}

// round 9
// speedup vs baseline: 1.2710x; 1.2710x over previous
#include <cuda_runtime.h>
#include <cuda_fp16.h>
#include <cstdint>
#include <cstddef>

#define B_ 16
#define L_ 16384
#define C_ 256
#define NH 8
#define FFN 512
#define EPS 1e-5f
#define SCALE_ATT 0.17677669529663687f
#define JOBS 2048

// k1 smem byte offsets (R6 layout)
#define O_A   0
#define O_B0  10240
#define O_MSM 0
#define O_SPC 67584
#define O_GQ  133120
#define O_IOR 141632
#define O_WSM 145728
#define O_ST  149824
#define O_MU  151872
#define O_RS  152384
#define O_CG  152896
#define O_CQC 152928
#define O_CS2 152960
#define O_CW  152992
#define O_BIP 153024
#define O_GIP 154048
#define O_BEI 155072
#define SM1   156096

__device__ float g_gq[B_ * NH * C_];
__device__ float g_G[B_ * NH];
__device__ float g_qc[B_ * NH];
__device__ float g_pmax[JOBS * NH];
__device__ float g_psum[JOBS * NH];
__device__ float g_pctx[(size_t)JOBS * NH * C_];
__device__ float g_ctxn[B_ * NH * C_];
__device__ __align__(16) __half g_wh[C_ * C_];   // W_ip^T fp16, n-major

__device__ __forceinline__ uint32_t smem_u32(const void* p) {
    uint32_t a;
    asm("{ .reg .u64 t; cvta.to.shared.u64 t, %1; cvt.u32.u64 %0, t; }" : "=r"(a) : "l"(p));
    return a;
}
__device__ __forceinline__ void ldmx4(uint32_t* r, uint32_t a) {
    asm volatile("ldmatrix.sync.aligned.m8n8.x4.shared.b16 {%0,%1,%2,%3}, [%4];"
        : "=r"(r[0]), "=r"(r[1]), "=r"(r[2]), "=r"(r[3]) : "r"(a));
}
__device__ __forceinline__ void mma16816(float* d, const uint32_t* a, uint32_t b0, uint32_t b1) {
    asm volatile("mma.sync.aligned.m16n8k16.row.col.f32.f16.f16.f32 "
        "{%0,%1,%2,%3}, {%4,%5,%6,%7}, {%8,%9}, {%0,%1,%2,%3};"
        : "+f"(d[0]), "+f"(d[1]), "+f"(d[2]), "+f"(d[3])
        : "r"(a[0]), "r"(a[1]), "r"(a[2]), "r"(a[3]), "r"(b0), "r"(b1));
}
#define CPA(dst, src) asm volatile("cp.async.cg.shared.global [%0], [%1], 16;" :: "r"(dst), "l"(src))
#define CPC() asm volatile("cp.async.commit_group;" ::: "memory")
#define CPW(n) asm volatile("cp.async.wait_group %0;" :: "n"(n) : "memory")

// ---- K0b: W_ip^T -> fp16, via coalesced smem-tile transpose ----
__global__ void k0b(const float* __restrict__ W_ip) {
    __shared__ float tile[32][33];
    const int tx = threadIdx.x, ty = threadIdx.y;
    const int r = blockIdx.y * 32 + ty;     // k index
    const int c = blockIdx.x * 32 + tx;     // n index
    tile[ty][tx] = W_ip[r * C_ + c];
    __syncthreads();
    // g_wh[n][k] with n = blockIdx.x*32+ty, k = blockIdx.y*32+tx (coalesced in tx)
    g_wh[(blockIdx.x * 32 + ty) * C_ + blockIdx.y * 32 + tx] = __float2half_rn(tile[tx][ty]);
}

// ---- dummy spacer so ncu (-s 5 -c 1) captures k1 ----
__global__ void kmid() {}

// ---- K0: LN(query)@W_q folded into gq/G/QC — 1024 thr, coalesced qkp ----
__global__ void __launch_bounds__(1024) k0(
    const float* __restrict__ query, const float* __restrict__ W_q,
    const float* __restrict__ b_q, const float* __restrict__ W_kv,
    const float* __restrict__ b_kv, const float* __restrict__ g_q,
    const float* __restrict__ be_q, const float* __restrict__ g_ip,
    const float* __restrict__ be_ip) {
    __shared__ float qn[C_], qs[C_], part[4 * C_], red[8], red2[8];
    __shared__ float wG[32 * 8], wQ[32 * 8];
    const int b = blockIdx.x, t = threadIdx.x, lane = t & 31, wid = t >> 5;

    if (t < C_) {
        float x = query[b * C_ + t];
        float s = x, s2 = x * x;
        #pragma unroll
        for (int o = 16; o >= 1; o >>= 1) {
            s += __shfl_xor_sync(~0u, s, o);
            s2 += __shfl_xor_sync(~0u, s2, o);
        }
        if (lane == 0) { red[wid] = s; red2[wid] = s2; }
    }
    __syncthreads();
    if (t < C_) {
        float su = 0.f, sq = 0.f;
        #pragma unroll
        for (int i = 0; i < 8; i++) { su += red[i]; sq += red2[i]; }
        float mean = su / C_, var = sq / C_ - mean * mean, rs = rsqrtf(var + EPS);
        qn[t] = (query[b * C_ + t] - mean) * rs * g_q[t] + be_q[t];
    }
    __syncthreads();

    // qs GEMV, 4-way k-split
    {
        const int tt = t & 255, sl = t >> 8;
        const float* W = W_q + tt;
        float a0 = 0.f, a1 = 0.f, a2 = 0.f, a3 = 0.f;
        const int c0 = sl * 64;
        #pragma unroll 4
        for (int c = 0; c < 64; c += 4) {
            a0 += qn[c0 + c] * W[(size_t)(c0 + c) * C_];
            a1 += qn[c0 + c + 1] * W[(size_t)(c0 + c + 1) * C_];
            a2 += qn[c0 + c + 2] * W[(size_t)(c0 + c + 2) * C_];
            a3 += qn[c0 + c + 3] * W[(size_t)(c0 + c + 3) * C_];
        }
        part[sl * C_ + tt] = (a0 + a1) + (a2 + a3);
    }
    __syncthreads();
    if (t < C_)
        qs[t] = b_q[t] + ((part[t] + part[C_ + t]) + (part[2 * C_ + t] + part[3 * C_ + t]));
    __syncthreads();

    // qkp: warp handles 8 c's; coalesced W_kv row reads + shuffle reduce
    {
        float gAcc = 0.f, qAcc = 0.f;   // lane h (h<8) accumulates head h
        const float gI_c[1] = {0};
        (void)gI_c;
        for (int i = 0; i < 8; i++) {
            const int c = wid * 8 + i;
            const float* wr = W_kv + (size_t)c * (2 * C_);
            float accs[8];
            #pragma unroll
            for (int h = 0; h < NH; h++)
                accs[h] = wr[h * 32 + lane] * qs[h * 32 + lane];
            #pragma unroll
            for (int h = 0; h < NH; h++) {
                float v = accs[h];
                #pragma unroll
                for (int o = 16; o >= 1; o >>= 1) v += __shfl_xor_sync(~0u, v, o);
                if (lane == h) {
                    float a = v * SCALE_ATT;
                    float gq = a * g_ip[c];
                    g_gq[(b * NH + h) * C_ + c] = gq;
                    gAcc += gq;
                    qAcc += a * be_ip[c];
                }
            }
        }
        if (lane < NH) { wG[wid * 8 + lane] = gAcc; wQ[wid * 8 + lane] = qAcc; }
    }
    __syncthreads();
    if (t < NH) {
        float G = 0.f, Q = 0.f;
        #pragma unroll 8
        for (int w = 0; w < 32; w++) { G += wG[w * 8 + t]; Q += wQ[w * 8 + t]; }
        float qb = 0.f;
        #pragma unroll 8
        for (int d = 0; d < 32; d++) qb += qs[t * 32 + d] * b_kv[t * 32 + d];
        g_G[b * NH + t] = G;
        g_qc[b * NH + t] = Q + qb * SCALE_ATT;
    }
}

// ---- K1: fp16 HMMA fused main kernel (R6 config: 128-row tile, occ 1) ----
__global__ void __launch_bounds__(512, 1)
k1(const float* __restrict__ mem, const float* __restrict__ ior,
   const float* __restrict__ b_ip, const float* __restrict__ g_ip,
   const float* __restrict__ be_ip) {
    extern __shared__ char sm[];
    float* S = (float*)sm;
    const uint32_t smb = smem_u32(sm);
    const int t = threadIdx.x, lane = t & 31, wid = t >> 5;
    const int rg = wid >> 1, cg = wid & 1;
    const int j = blockIdx.x, b = j >> 7, row0 = (j & 127) << 7;

    for (int i = t; i < NH * C_; i += 512)
        S[(O_GQ >> 2) + (i >> 8) * 264 + (i & 255)] = g_gq[b * NH * C_ + i];
    if (t < NH) {
        S[(O_CG >> 2) + t] = g_G[b * NH + t];
        S[(O_CQC >> 2) + t] = g_qc[b * NH + t];
    }
    for (int i = t; i < NH * 128; i += 512)
        S[(O_IOR >> 2) + i] = ior[(size_t)(b * NH + (i >> 7)) * L_ + row0 + (i & 127)];
    if (t < C_) {
        S[(O_BIP >> 2) + t] = b_ip[t];
        S[(O_GIP >> 2) + t] = g_ip[t];
        S[(O_BEI >> 2) + t] = be_ip[t];
    }

    const float4* mem4 = (const float4*)mem;
    const int ar = t >> 2, aq = t & 3;
    const size_t abase = (size_t)(b * L_ + row0 + ar) * 64;
    float4 av0 = mem4[abase + aq * 2], av1 = mem4[abase + aq * 2 + 1];

    const int bn = t >> 1, bf = t & 1;
    {
        const char* sH = (const char*)g_wh + ((size_t)bn * 256 + bf * 16) * 2;
        uint32_t d0 = smb + O_B0 + bn * 80 + bf * 32;
        CPA(d0, sH); CPA(d0 + 16, sH + 16);
        CPC();
    }

    float d[16][4];
    #pragma unroll
    for (int i = 0; i < 16; i++)
        #pragma unroll
        for (int q = 0; q < 4; q++) d[i][q] = 0.f;

    const int lg = lane >> 3, lr = lane & 7;
    const uint32_t aAddr = smb + O_A + (rg * 16 + ((lg & 1) << 3) + lr) * 80 + (lg >> 1) * 16;
    const uint32_t bOff = (cg * 128 + ((lg >> 1) << 3) + lr) * 80 + (lg & 1) * 16;

    for (int kc = 0; kc < 8; kc++) {
        __syncthreads();
        {
            __half2 h0 = __floats2half2_rn(av0.x, av0.y);
            __half2 h1 = __floats2half2_rn(av0.z, av0.w);
            __half2 h2 = __floats2half2_rn(av1.x, av1.y);
            __half2 h3 = __floats2half2_rn(av1.z, av1.w);
            *(uint4*)(sm + O_A + ar * 80 + aq * 16) =
                make_uint4(*(uint32_t*)&h0, *(uint32_t*)&h1, *(uint32_t*)&h2, *(uint32_t*)&h3);
        }
        if (kc < 7) {
            av0 = mem4[abase + (kc + 1) * 8 + aq * 2];
            av1 = mem4[abase + (kc + 1) * 8 + aq * 2 + 1];
            const char* sH = (const char*)g_wh + ((size_t)bn * 256 + (kc + 1) * 32 + bf * 16) * 2;
            uint32_t d0 = smb + O_B0 + ((kc + 1) & 1) * 20480 + bn * 80 + bf * 32;
            CPA(d0, sH); CPA(d0 + 16, sH + 16);
            CPC();
            CPW(1);
        } else {
            CPW(0);
        }
        __syncthreads();

        uint32_t bufB = smb + O_B0 + (kc & 1) * 20480 + bOff;
        #pragma unroll
        for (int ks = 0; ks < 2; ks++) {
            uint32_t ah[4];
            ldmx4(ah, aAddr + ks * 32);
            uint32_t bh[8][4];
            #pragma unroll
            for (int jt = 0; jt < 8; jt++)
                ldmx4(bh[jt], bufB + jt * 1280 + ks * 32);
            #pragma unroll
            for (int jt = 0; jt < 8; jt++) {
                mma16816(d[2 * jt], ah, bh[jt][0], bh[jt][1]);
                mma16816(d[2 * jt + 1], ah, bh[jt][2], bh[jt][3]);
            }
        }
    }
    __syncthreads();

    // pass 1: bias+relu, stats, msm write, score partials
    const int r0 = rg * 16 + (lane >> 2), r1 = r0 + 8;
    const int cq = (lane & 3) * 2;
    float s0 = 0.f, q0 = 0.f, s1 = 0.f, q1 = 0.f;
    float p0[NH], p1[NH];
    #pragma unroll
    for (int h = 0; h < NH; h++) { p0[h] = 0.f; p1[h] = 0.f; }
    #pragma unroll
    for (int nt = 0; nt < 16; nt++) {
        int c = cg * 128 + nt * 8 + cq;
        float2 bb = *(float2*)&S[(O_BIP >> 2) + c];
        float x0 = fmaxf(d[nt][0] + bb.x, 0.f), x1 = fmaxf(d[nt][1] + bb.y, 0.f);
        float y0 = fmaxf(d[nt][2] + bb.x, 0.f), y1 = fmaxf(d[nt][3] + bb.y, 0.f);
        s0 += x0 + x1; q0 += x0 * x0 + x1 * x1;
        s1 += y0 + y1; q1 += y0 * y0 + y1 * y1;
        *(__half2*)(sm + O_MSM + (r0 * 264 + c) * 2) = __floats2half2_rn(x0, x1);
        *(__half2*)(sm + O_MSM + (r1 * 264 + c) * 2) = __floats2half2_rn(y0, y1);
        #pragma unroll
        for (int h = 0; h < NH; h++) {
            float2 qv = *(float2*)&S[(O_GQ >> 2) + h * 264 + c];
            p0[h] += x0 * qv.x + x1 * qv.y;
            p1[h] += y0 * qv.x + y1 * qv.y;
        }
    }
    #pragma unroll
    for (int o = 1; o <= 2; o <<= 1) {
        s0 += __shfl_xor_sync(~0u, s0, o); q0 += __shfl_xor_sync(~0u, q0, o);
        s1 += __shfl_xor_sync(~0u, s1, o); q1 += __shfl_xor_sync(~0u, q1, o);
        #pragma unroll
        for (int h = 0; h < NH; h++) {
            p0[h] += __shfl_xor_sync(~0u, p0[h], o);
            p1[h] += __shfl_xor_sync(~0u, p1[h], o);
        }
    }
    if ((lane & 3) == 0) {
        S[(O_ST >> 2) + r0 * 2 + cg] = s0; S[(O_ST >> 2) + 256 + r0 * 2 + cg] = q0;
        S[(O_ST >> 2) + r1 * 2 + cg] = s1; S[(O_ST >> 2) + 256 + r1 * 2 + cg] = q1;
        #pragma unroll
        for (int h = 0; h < NH; h++) {
            S[(O_SPC >> 2) + (r0 * 8 + h) * 2 + cg] = p0[h];
            S[(O_SPC >> 2) + (r1 * 8 + h) * 2 + cg] = p1[h];
        }
    }
    __syncthreads();

    // score combine
    for (int e = t; e < NH * 128; e += 512) {
        int h = e >> 7, rr = e & 127;
        float P = S[(O_SPC >> 2) + (rr * 8 + h) * 2] + S[(O_SPC >> 2) + (rr * 8 + h) * 2 + 1];
        float su = S[(O_ST >> 2) + rr * 2] + S[(O_ST >> 2) + rr * 2 + 1];
        float sq = S[(O_ST >> 2) + 256 + rr * 2] + S[(O_ST >> 2) + 256 + rr * 2 + 1];
        float mu = su * (1.f / C_);
        float rs = rsqrtf(sq * (1.f / C_) - mu * mu + EPS);
        if (h == 0) { S[(O_MU >> 2) + rr] = mu; S[(O_RS >> 2) + rr] = rs; }
        S[(O_WSM >> 2) + e] = (rs * (P - mu * S[(O_CG >> 2) + h]) + S[(O_CQC >> 2) + h])
                              * S[(O_IOR >> 2) + e];
    }
    __syncthreads();

    // per-tile softmax
    if (wid < NH) {
        float v0 = S[(O_WSM >> 2) + wid * 128 + lane];
        float v1 = S[(O_WSM >> 2) + wid * 128 + 32 + lane];
        float v2 = S[(O_WSM >> 2) + wid * 128 + 64 + lane];
        float v3 = S[(O_WSM >> 2) + wid * 128 + 96 + lane];
        float mx = fmaxf(fmaxf(v0, v1), fmaxf(v2, v3));
        #pragma unroll
        for (int o = 16; o >= 1; o >>= 1) mx = fmaxf(mx, __shfl_xor_sync(~0u, mx, o));
        float e0 = __expf(v0 - mx), e1 = __expf(v1 - mx);
        float e2 = __expf(v2 - mx), e3 = __expf(v3 - mx);
        float rs0 = S[(O_RS >> 2) + lane],      mu0 = S[(O_MU >> 2) + lane];
        float rs1 = S[(O_RS >> 2) + 32 + lane], mu1 = S[(O_MU >> 2) + 32 + lane];
        float rs2 = S[(O_RS >> 2) + 64 + lane], mu2 = S[(O_MU >> 2) + 64 + lane];
        float rs3 = S[(O_RS >> 2) + 96 + lane], mu3 = S[(O_MU >> 2) + 96 + lane];
        S[(O_WSM >> 2) + wid * 128 + lane]      = e0 * rs0;
        S[(O_WSM >> 2) + wid * 128 + 32 + lane] = e1 * rs1;
        S[(O_WSM >> 2) + wid * 128 + 64 + lane] = e2 * rs2;
        S[(O_WSM >> 2) + wid * 128 + 96 + lane] = e3 * rs3;
        float es = (e0 + e1) + (e2 + e3);
        float s2 = e0 * rs0 * mu0 + e1 * rs1 * mu1 + e2 * rs2 * mu2 + e3 * rs3 * mu3;
        #pragma unroll
        for (int o = 16; o >= 1; o >>= 1) {
            es += __shfl_xor_sync(~0u, es, o);
            s2 += __shfl_xor_sync(~0u, s2, o);
        }
        if (lane == 0) {
            g_pmax[j * NH + wid] = mx;
            g_psum[j * NH + wid] = es;
            S[(O_CW >> 2) + wid] = es;
            S[(O_CS2 >> 2) + wid] = s2;
        }
    }
    __syncthreads();

    // ctx partial
    {
        const int c4 = t & 63, sl = t >> 6;
        float4 a8[NH];
        #pragma unroll
        for (int h = 0; h < NH; h++) a8[h] = make_float4(0.f, 0.f, 0.f, 0.f);
        for (int r = sl * 16; r < sl * 16 + 16; r++) {
            uint2 u = *(uint2*)(sm + O_MSM + (r * 264 + c4 * 4) * 2);
            float2 f01 = __half22float2(*(__half2*)&u.x);
            float2 f23 = __half22float2(*(__half2*)&u.y);
            #pragma unroll
            for (int h = 0; h < NH; h++) {
                float w = S[(O_WSM >> 2) + h * 128 + r];
                a8[h].x += w * f01.x; a8[h].y += w * f01.y;
                a8[h].z += w * f23.x; a8[h].w += w * f23.y;
            }
        }
        #pragma unroll
        for (int h = 0; h < NH; h++)
            *(float4*)&S[(O_SPC >> 2) + ((sl * 8 + h) * 64 + c4) * 4] = a8[h];
        __syncthreads();
        const int hh = t >> 6, cc = t & 63;
        float4 s4 = make_float4(0.f, 0.f, 0.f, 0.f);
        #pragma unroll
        for (int s2i = 0; s2i < 8; s2i++) {
            float4 v = *(float4*)&S[(O_SPC >> 2) + ((s2i * 8 + hh) * 64 + cc) * 4];
            s4.x += v.x; s4.y += v.y; s4.z += v.z; s4.w += v.w;
        }
        float4 gg = *(float4*)&S[(O_GIP >> 2) + cc * 4];
        float4 ee = *(float4*)&S[(O_BEI >> 2) + cc * 4];
        float sh = S[(O_CS2 >> 2) + hh], Wh = S[(O_CW >> 2) + hh];
        float4 outv;
        outv.x = gg.x * (s4.x - sh) + ee.x * Wh;
        outv.y = gg.y * (s4.y - sh) + ee.y * Wh;
        outv.z = gg.z * (s4.z - sh) + ee.z * Wh;
        outv.w = gg.w * (s4.w - sh) + ee.w * Wh;
        ((float4*)g_pctx)[(size_t)j * 512 + hh * 64 + cc] = outv;
    }
}

// ---- K2a: parallel softmax-combine of 128 partials, one block per (b,h) ----
__global__ void k2a() {
    __shared__ float pm[128], ps[128], ef[128], red[4], red2[4], cacc[4 * 256];
    const int b = blockIdx.x >> 3, h = blockIdx.x & 7;
    const int t = threadIdx.x, lane = t & 31;
    const int col = t & 255, sl = t >> 8;
    if (t < 128) {
        pm[t] = g_pmax[(b * 128 + t) * NH + h];
        ps[t] = g_psum[(b * 128 + t) * NH + h];
    }
    __syncthreads();
    if (t < 128) {
        float v = pm[t];
        #pragma unroll
        for (int o = 16; o >= 1; o >>= 1) v = fmaxf(v, __shfl_xor_sync(~0u, v, o));
        if (lane == 0) red[t >> 5] = v;
    }
    __syncthreads();
    float gmax = fmaxf(fmaxf(red[0], red[1]), fmaxf(red[2], red[3]));
    if (t < 128) ef[t] = __expf(pm[t] - gmax);
    __syncthreads();
    if (t < 128) {
        float v = ps[t] * ef[t];
        #pragma unroll
        for (int o = 16; o >= 1; o >>= 1) v += __shfl_xor_sync(~0u, v, o);
        if (lane == 0) red2[t >> 5] = v;
    }
    __syncthreads();
    float acc = 0.f;
    const float* p = g_pctx + ((size_t)(b * 128 + sl * 32) * NH + h) * C_ + col;
    #pragma unroll 4
    for (int ch = 0; ch < 32; ch++)
        acc += ef[sl * 32 + ch] * p[(size_t)ch * NH * C_];
    cacc[sl * 256 + col] = acc;
    __syncthreads();
    if (sl == 0) {
        float inv = 1.f / (red2[0] + red2[1] + red2[2] + red2[3]);
        float tot = cacc[col] + cacc[256 + col] + cacc[512 + col] + cacc[768 + col];
        g_ctxn[(b * NH + h) * C_ + col] = tot * inv;
    }
}

// ---- K2b: V-proj + residual + LN + FFN, 1024 threads with k-split ----
__global__ void __launch_bounds__(1024) k2b(
    const float* __restrict__ query, const float* __restrict__ W_kv,
    const float* __restrict__ b_kv, const float* __restrict__ g_f,
    const float* __restrict__ be_f, const float* __restrict__ W1,
    const float* __restrict__ b1, const float* __restrict__ W2,
    const float* __restrict__ b2, float* __restrict__ out) {
    __shared__ float ctxn[NH * C_], xs[C_], hs[C_], us[FFN], part[1024], red[8], red2[8];
    const int b = blockIdx.x, t = threadIdx.x, lane = t & 31, wid = t >> 5;
    for (int i = t; i < NH * C_; i += 1024) ctxn[i] = g_ctxn[b * NH * C_ + i];
    __syncthreads();

    // V-proj, 4-way k-split
    {
        const int tt = t & 255, sl = t >> 8;
        const int h = tt >> 5;
        const float* W = W_kv + C_ + tt;
        const float* cx = ctxn + h * C_ + sl * 64;
        float a0 = 0.f, a1 = 0.f, a2 = 0.f, a3 = 0.f;
        #pragma unroll 4
        for (int c = 0; c < 64; c += 4) {
            a0 += cx[c] * W[(size_t)(sl * 64 + c) * (2 * C_)];
            a1 += cx[c + 1] * W[(size_t)(sl * 64 + c + 1) * (2 * C_)];
            a2 += cx[c + 2] * W[(size_t)(sl * 64 + c + 2) * (2 * C_)];
            a3 += cx[c + 3] * W[(size_t)(sl * 64 + c + 3) * (2 * C_)];
        }
        part[sl * 256 + tt] = (a0 + a1) + (a2 + a3);
    }
    __syncthreads();
    if (t < C_) {
        float x = b_kv[C_ + t] + ((part[t] + part[256 + t]) + (part[512 + t] + part[768 + t]))
                + query[b * C_ + t];
        xs[t] = x;
        float s = x, s2 = x * x;
        #pragma unroll
        for (int o = 16; o >= 1; o >>= 1) {
            s += __shfl_xor_sync(~0u, s, o);
            s2 += __shfl_xor_sync(~0u, s2, o);
        }
        if (lane == 0) { red[wid] = s; red2[wid] = s2; }
    }
    __syncthreads();
    if (t < C_) {
        float su = 0.f, sq = 0.f;
        #pragma unroll
        for (int i = 0; i < 8; i++) { su += red[i]; sq += red2[i]; }
        float mean = su / C_, var = sq / C_ - mean * mean, rs = rsqrtf(var + EPS);
        hs[t] = (xs[t] - mean) * rs * g_f[t] + be_f[t];
    }
    __syncthreads();

    // FFN1, 2-way k-split
    {
        const int f = t & 511, sl = t >> 9;
        const float* W = W1 + f;
        const int c0 = sl * 128;
        float a0 = 0.f, a1 = 0.f, a2 = 0.f, a3 = 0.f;
        #pragma unroll 4
        for (int c = 0; c < 128; c += 4) {
            a0 += hs[c0 + c] * W[(size_t)(c0 + c) * FFN];
            a1 += hs[c0 + c + 1] * W[(size_t)(c0 + c + 1) * FFN];
            a2 += hs[c0 + c + 2] * W[(size_t)(c0 + c + 2) * FFN];
            a3 += hs[c0 + c + 3] * W[(size_t)(c0 + c + 3) * FFN];
        }
        part[sl * 512 + f] = (a0 + a1) + (a2 + a3);
    }
    __syncthreads();
    if (t < FFN) {
        float u = b1[t] + part[t] + part[512 + t];
        us[t] = 0.5f * u * (1.f + erff(u * 0.70710678118654752f));
    }
    __syncthreads();

    // FFN2, 4-way k-split
    {
        const int tt = t & 255, sl = t >> 8;
        const float* W = W2 + tt;
        const int f0 = sl * 128;
        float a0 = 0.f, a1 = 0.f, a2 = 0.f, a3 = 0.f;
        #pragma unroll 4
        for (int f = 0; f < 128; f += 4) {
            a0 += us[f0 + f] * W[(size_t)(f0 + f) * C_];
            a1 += us[f0 + f + 1] * W[(size_t)(f0 + f + 1) * C_];
            a2 += us[f0 + f + 2] * W[(size_t)(f0 + f + 2) * C_];
            a3 += us[f0 + f + 3] * W[(size_t)(f0 + f + 3) * C_];
        }
        part[sl * 256 + tt] = (a0 + a1) + (a2 + a3);
    }
    __syncthreads();
    if (t < C_)
        out[b * C_ + t] = xs[t] + b2[t]
            + ((part[t] + part[256 + t]) + (part[512 + t] + part[768 + t]));
}

extern "C" void kernel_launch(void* const* d_in, const int* in_sizes, int n_in,
                              void* d_out, int out_size) {
    const float* query = (const float*)d_in[0];
    const float* mem   = (const float*)d_in[1];
    const float* ior   = (const float*)d_in[2];
    const float* W_ip  = (const float*)d_in[3];
    const float* b_ip  = (const float*)d_in[4];
    const float* g_ip  = (const float*)d_in[5];
    const float* be_ip = (const float*)d_in[6];
    const float* W_q   = (const float*)d_in[7];
    const float* b_q   = (const float*)d_in[8];
    const float* W_kv  = (const float*)d_in[9];
    const float* b_kv  = (const float*)d_in[10];
    const float* g_q   = (const float*)d_in[11];
    const float* be_q  = (const float*)d_in[12];
    const float* g_f   = (const float*)d_in[13];
    const float* be_f  = (const float*)d_in[14];
    const float* W1    = (const float*)d_in[15];
    const float* b1    = (const float*)d_in[16];
    const float* W2    = (const float*)d_in[17];
    const float* b2    = (const float*)d_in[18];

    cudaFuncSetAttribute(k1, cudaFuncAttributeMaxDynamicSharedMemorySize, SM1);
    k0b<<<dim3(8, 8), dim3(32, 32)>>>(W_ip);
    k0<<<B_, 1024>>>(query, W_q, b_q, W_kv, b_kv, g_q, be_q, g_ip, be_ip);
    kmid<<<1, 32>>>();
    k1<<<JOBS, 512, SM1>>>(mem, ior, b_ip, g_ip, be_ip);
    k2a<<<B_ * NH, 1024>>>();
    k2b<<<B_, 1024>>>(query, W_kv, b_kv, g_f, be_f, W1, b1, W2, b2, (float*)d_out);
}

// round 10
// speedup vs baseline: 1.6674x; 1.3119x over previous
#include <cuda_runtime.h>
#include <cuda_fp16.h>
#include <cstdint>
#include <cstddef>

#define B_ 16
#define L_ 16384
#define C_ 256
#define NH 8
#define FFN 512
#define EPS 1e-5f
#define SCALE_ATT 0.17677669529663687f
#define JOBS 2048

// k1 smem byte offsets
#define O_A   0         /* A fp16: 128 x 40 halves */
#define O_B0  10240     /* B fp16 double buffer: 2 x 20480 */
#define O_MSM 0         /* m^ fp16 [128][264] = 67584, overlays GEMM bufs */
#define O_SPC 67584     /* score MMA partials [2][128][8] = 8192 */
#define O_QS  75776     /* row sumsq partials [128][4] = 2048 */
#define O_WH  83968     /* w~ fp16 [8][136] = 2176 */
#define O_GQ  133120    /* gq fp16 [8][264] = 4224 */
#define O_IOR 141632    /* [8][128] float */
#define O_SC  145728    /* scores float [8][128] */
#define O_ST  149824    /* row sum partials [128][4] = 2048 */
#define O_MU  151872
#define O_RS  152384
#define O_CG  152896
#define O_CQC 152928
#define O_CS2 152960
#define O_CW  152992
#define O_BIP 153024
#define O_GIP 154048
#define O_BEI 155072
#define SM1   156096

__device__ __half g_gqh[B_ * NH * C_];
__device__ float g_G[B_ * NH];
__device__ float g_qc[B_ * NH];
__device__ float g_pmax[JOBS * NH];
__device__ float g_psum[JOBS * NH];
__device__ float g_pctx[(size_t)JOBS * NH * C_];
__device__ float g_ctxn[B_ * NH * C_];
__device__ __align__(16) __half g_wh[C_ * C_];   // W_ip^T fp16, n-major

__device__ __forceinline__ uint32_t smem_u32(const void* p) {
    uint32_t a;
    asm("{ .reg .u64 t; cvta.to.shared.u64 t, %1; cvt.u32.u64 %0, t; }" : "=r"(a) : "l"(p));
    return a;
}
__device__ __forceinline__ void ldmx4(uint32_t* r, uint32_t a) {
    asm volatile("ldmatrix.sync.aligned.m8n8.x4.shared.b16 {%0,%1,%2,%3}, [%4];"
        : "=r"(r[0]), "=r"(r[1]), "=r"(r[2]), "=r"(r[3]) : "r"(a));
}
__device__ __forceinline__ void ldmx4t(uint32_t* r, uint32_t a) {
    asm volatile("ldmatrix.sync.aligned.m8n8.x4.trans.shared.b16 {%0,%1,%2,%3}, [%4];"
        : "=r"(r[0]), "=r"(r[1]), "=r"(r[2]), "=r"(r[3]) : "r"(a));
}
__device__ __forceinline__ void ldmx2(uint32_t* r, uint32_t a) {
    asm volatile("ldmatrix.sync.aligned.m8n8.x2.shared.b16 {%0,%1}, [%2];"
        : "=r"(r[0]), "=r"(r[1]) : "r"(a));
}
__device__ __forceinline__ void mma16816(float* d, const uint32_t* a, uint32_t b0, uint32_t b1) {
    asm volatile("mma.sync.aligned.m16n8k16.row.col.f32.f16.f16.f32 "
        "{%0,%1,%2,%3}, {%4,%5,%6,%7}, {%8,%9}, {%0,%1,%2,%3};"
        : "+f"(d[0]), "+f"(d[1]), "+f"(d[2]), "+f"(d[3])
        : "r"(a[0]), "r"(a[1]), "r"(a[2]), "r"(a[3]), "r"(b0), "r"(b1));
}
#define CPA(dst, src) asm volatile("cp.async.cg.shared.global [%0], [%1], 16;" :: "r"(dst), "l"(src))
#define CPC() asm volatile("cp.async.commit_group;" ::: "memory")
#define CPW(n) asm volatile("cp.async.wait_group %0;" :: "n"(n) : "memory")

// ---- K0b: W_ip^T -> fp16 via coalesced smem-tile transpose ----
__global__ void k0b(const float* __restrict__ W_ip) {
    __shared__ float tile[32][33];
    const int tx = threadIdx.x, ty = threadIdx.y;
    tile[ty][tx] = W_ip[(blockIdx.y * 32 + ty) * C_ + blockIdx.x * 32 + tx];
    __syncthreads();
    g_wh[(blockIdx.x * 32 + ty) * C_ + blockIdx.y * 32 + tx] = __float2half_rn(tile[tx][ty]);
}

// ---- spacer so ncu (-s 5 -c 1) captures k1 ----
__global__ void kmid() {}

// ---- K0: LN(query)@W_q folded into gqh/G/QC ----
__global__ void __launch_bounds__(1024) k0(
    const float* __restrict__ query, const float* __restrict__ W_q,
    const float* __restrict__ b_q, const float* __restrict__ W_kv,
    const float* __restrict__ b_kv, const float* __restrict__ g_q,
    const float* __restrict__ be_q, const float* __restrict__ g_ip,
    const float* __restrict__ be_ip) {
    __shared__ float qn[C_], qs[C_], part[4 * C_], red[8], red2[8];
    __shared__ float wG[32 * 8], wQ[32 * 8];
    const int b = blockIdx.x, t = threadIdx.x, lane = t & 31, wid = t >> 5;

    if (t < C_) {
        float x = query[b * C_ + t];
        float s = x, s2 = x * x;
        #pragma unroll
        for (int o = 16; o >= 1; o >>= 1) {
            s += __shfl_xor_sync(~0u, s, o);
            s2 += __shfl_xor_sync(~0u, s2, o);
        }
        if (lane == 0) { red[wid] = s; red2[wid] = s2; }
    }
    __syncthreads();
    if (t < C_) {
        float su = 0.f, sq = 0.f;
        #pragma unroll
        for (int i = 0; i < 8; i++) { su += red[i]; sq += red2[i]; }
        float mean = su / C_, var = sq / C_ - mean * mean, rs = rsqrtf(var + EPS);
        qn[t] = (query[b * C_ + t] - mean) * rs * g_q[t] + be_q[t];
    }
    __syncthreads();
    {
        const int tt = t & 255, sl = t >> 8;
        const float* W = W_q + tt;
        float a0 = 0.f, a1 = 0.f, a2 = 0.f, a3 = 0.f;
        const int c0 = sl * 64;
        #pragma unroll 4
        for (int c = 0; c < 64; c += 4) {
            a0 += qn[c0 + c] * W[(size_t)(c0 + c) * C_];
            a1 += qn[c0 + c + 1] * W[(size_t)(c0 + c + 1) * C_];
            a2 += qn[c0 + c + 2] * W[(size_t)(c0 + c + 2) * C_];
            a3 += qn[c0 + c + 3] * W[(size_t)(c0 + c + 3) * C_];
        }
        part[sl * C_ + tt] = (a0 + a1) + (a2 + a3);
    }
    __syncthreads();
    if (t < C_)
        qs[t] = b_q[t] + ((part[t] + part[C_ + t]) + (part[2 * C_ + t] + part[3 * C_ + t]));
    __syncthreads();
    {
        float gAcc = 0.f, qAcc = 0.f;
        for (int i = 0; i < 8; i++) {
            const int c = wid * 8 + i;
            const float* wr = W_kv + (size_t)c * (2 * C_);
            float accs[8];
            #pragma unroll
            for (int h = 0; h < NH; h++)
                accs[h] = wr[h * 32 + lane] * qs[h * 32 + lane];
            #pragma unroll
            for (int h = 0; h < NH; h++) {
                float v = accs[h];
                #pragma unroll
                for (int o = 16; o >= 1; o >>= 1) v += __shfl_xor_sync(~0u, v, o);
                if (lane == h) {
                    float a = v * SCALE_ATT;
                    __half gh = __float2half_rn(a * g_ip[c]);
                    g_gqh[(b * NH + h) * C_ + c] = gh;
                    gAcc += __half2float(gh);
                    qAcc += a * be_ip[c];
                }
            }
        }
        if (lane < NH) { wG[wid * 8 + lane] = gAcc; wQ[wid * 8 + lane] = qAcc; }
    }
    __syncthreads();
    if (t < NH) {
        float G = 0.f, Q = 0.f;
        #pragma unroll 8
        for (int w = 0; w < 32; w++) { G += wG[w * 8 + t]; Q += wQ[w * 8 + t]; }
        float qb = 0.f;
        #pragma unroll 8
        for (int d = 0; d < 32; d++) qb += qs[t * 32 + d] * b_kv[t * 32 + d];
        g_G[b * NH + t] = G;
        g_qc[b * NH + t] = Q + qb * SCALE_ATT;
    }
}

// ---- K1: fp16 HMMA fused main kernel, 4x4 warp tiling, MMA epilogue ----
__global__ void __launch_bounds__(512, 1)
k1(const float* __restrict__ mem, const float* __restrict__ ior,
   const float* __restrict__ b_ip, const float* __restrict__ g_ip,
   const float* __restrict__ be_ip) {
    extern __shared__ char sm[];
    float* S = (float*)sm;
    const uint32_t smb = smem_u32(sm);
    const int t = threadIdx.x, lane = t & 31, wid = t >> 5;
    const int rg = wid >> 2, cg = wid & 3;    // 4x4 warp grid
    const int j = blockIdx.x, b = j >> 7, row0 = (j & 127) << 7;

    // per-block init
    for (int i = t; i < NH * C_; i += 512)
        *(__half*)(sm + O_GQ + (((i >> 8) * 264 + (i & 255)) * 2)) = g_gqh[b * NH * C_ + i];
    if (t < NH) {
        S[(O_CG >> 2) + t] = g_G[b * NH + t];
        S[(O_CQC >> 2) + t] = g_qc[b * NH + t];
    }
    for (int i = t; i < NH * 128; i += 512)
        S[(O_IOR >> 2) + i] = ior[(size_t)(b * NH + (i >> 7)) * L_ + row0 + (i & 127)];
    if (t < C_) {
        S[(O_BIP >> 2) + t] = b_ip[t];
        S[(O_GIP >> 2) + t] = g_ip[t];
        S[(O_BEI >> 2) + t] = be_ip[t];
    }

    // ---- GEMM: [128,256] = A[128,256] @ B^T, fp16, K-chunks of 32 ----
    const float4* mem4 = (const float4*)mem;
    const int ar = t >> 2, aq = t & 3;
    const size_t abase = (size_t)(b * L_ + row0 + ar) * 64;
    float4 av0 = mem4[abase + aq * 2], av1 = mem4[abase + aq * 2 + 1];

    const int bn = t >> 1, bf = t & 1;
    {
        const char* sH = (const char*)g_wh + ((size_t)bn * 256 + bf * 16) * 2;
        uint32_t d0 = smb + O_B0 + bn * 80 + bf * 32;
        CPA(d0, sH); CPA(d0 + 16, sH + 16);
        CPC();
    }

    float d[16][4];
    #pragma unroll
    for (int i = 0; i < 16; i++)
        #pragma unroll
        for (int q = 0; q < 4; q++) d[i][q] = 0.f;

    const int lg = lane >> 3, lr = lane & 7;
    const uint32_t aAddr = smb + O_A + (rg * 32 + ((lg & 1) << 3) + lr) * 80 + (lg >> 1) * 16;
    const uint32_t bOff = (cg * 64 + ((lg >> 1) << 3) + lr) * 80 + (lg & 1) * 16;

    for (int kc = 0; kc < 8; kc++) {
        __syncthreads();
        {
            __half2 h0 = __floats2half2_rn(av0.x, av0.y);
            __half2 h1 = __floats2half2_rn(av0.z, av0.w);
            __half2 h2 = __floats2half2_rn(av1.x, av1.y);
            __half2 h3 = __floats2half2_rn(av1.z, av1.w);
            *(uint4*)(sm + O_A + ar * 80 + aq * 16) =
                make_uint4(*(uint32_t*)&h0, *(uint32_t*)&h1, *(uint32_t*)&h2, *(uint32_t*)&h3);
        }
        if (kc < 7) {
            av0 = mem4[abase + (kc + 1) * 8 + aq * 2];
            av1 = mem4[abase + (kc + 1) * 8 + aq * 2 + 1];
            const char* sH = (const char*)g_wh + ((size_t)bn * 256 + (kc + 1) * 32 + bf * 16) * 2;
            uint32_t d0 = smb + O_B0 + ((kc + 1) & 1) * 20480 + bn * 80 + bf * 32;
            CPA(d0, sH); CPA(d0 + 16, sH + 16);
            CPC();
            CPW(1);
        } else {
            CPW(0);
        }
        __syncthreads();

        uint32_t bufB = smb + O_B0 + (kc & 1) * 20480 + bOff;
        #pragma unroll
        for (int ks = 0; ks < 2; ks++) {
            uint32_t a[2][4];
            ldmx4(a[0], aAddr + ks * 32);
            ldmx4(a[1], aAddr + 1280 + ks * 32);
            uint32_t bh[4][4];
            #pragma unroll
            for (int jt = 0; jt < 4; jt++)
                ldmx4(bh[jt], bufB + jt * 1280 + ks * 32);
            #pragma unroll
            for (int mi = 0; mi < 2; mi++)
                #pragma unroll
                for (int jt = 0; jt < 4; jt++) {
                    mma16816(d[mi * 8 + 2 * jt], a[mi], bh[jt][0], bh[jt][1]);
                    mma16816(d[mi * 8 + 2 * jt + 1], a[mi], bh[jt][2], bh[jt][3]);
                }
        }
    }
    __syncthreads();

    // ---- pass 1: bias+relu, row stats, msm fp16 write ----
    const int cq = (lane & 3) * 2;
    #pragma unroll
    for (int mi = 0; mi < 2; mi++) {
        int rA = rg * 32 + mi * 16 + (lane >> 2), rB = rA + 8;
        float sA = 0.f, qA = 0.f, sB = 0.f, qB = 0.f;
        #pragma unroll
        for (int nj = 0; nj < 8; nj++) {
            int c = cg * 64 + (nj >> 1) * 16 + (nj & 1) * 8 + cq;
            float2 bb = *(float2*)&S[(O_BIP >> 2) + c];
            float* dd = d[mi * 8 + nj];
            float x0 = fmaxf(dd[0] + bb.x, 0.f), x1 = fmaxf(dd[1] + bb.y, 0.f);
            float y0 = fmaxf(dd[2] + bb.x, 0.f), y1 = fmaxf(dd[3] + bb.y, 0.f);
            sA += x0 + x1; qA += x0 * x0 + x1 * x1;
            sB += y0 + y1; qB += y0 * y0 + y1 * y1;
            *(__half2*)(sm + O_MSM + (rA * 264 + c) * 2) = __floats2half2_rn(x0, x1);
            *(__half2*)(sm + O_MSM + (rB * 264 + c) * 2) = __floats2half2_rn(y0, y1);
        }
        #pragma unroll
        for (int o = 1; o <= 2; o <<= 1) {
            sA += __shfl_xor_sync(~0u, sA, o); qA += __shfl_xor_sync(~0u, qA, o);
            sB += __shfl_xor_sync(~0u, sB, o); qB += __shfl_xor_sync(~0u, qB, o);
        }
        if ((lane & 3) == 0) {
            S[(O_ST >> 2) + rA * 4 + cg] = sA; S[(O_QS >> 2) + rA * 4 + cg] = qA;
            S[(O_ST >> 2) + rB * 4 + cg] = sB; S[(O_QS >> 2) + rB * 4 + cg] = qB;
        }
    }
    __syncthreads();

    // ---- score MMA: P[128,8] = msm @ gq^T, k-split across 2 warp groups ----
    {
        const int mt = wid & 7, khalf = wid >> 3;
        float dS[4] = {0.f, 0.f, 0.f, 0.f};
        uint32_t aA = smb + O_MSM + ((mt * 16 + ((lg & 1) << 3) + lr) * 264 + (lg >> 1) * 8) * 2;
        uint32_t bA = smb + O_GQ + ((lane & 7) * 264 + ((lane >> 3) & 1) * 8) * 2;
        #pragma unroll
        for (int kk = 0; kk < 8; kk++) {
            int k = khalf * 128 + kk * 16;
            uint32_t a[4], bb[2];
            ldmx4(a, aA + k * 2);
            ldmx2(bb, bA + k * 2);
            mma16816(dS, a, bb[0], bb[1]);
        }
        int r = mt * 16 + (lane >> 2), h0 = (lane & 3) * 2;
        *(float2*)&S[(O_SPC >> 2) + khalf * 1024 + r * 8 + h0] = make_float2(dS[0], dS[1]);
        *(float2*)&S[(O_SPC >> 2) + khalf * 1024 + (r + 8) * 8 + h0] = make_float2(dS[2], dS[3]);
    }
    __syncthreads();

    // ---- score combine: sc = (rs*(P - mu*G) + QC) * ior ----
    for (int e = t; e < NH * 128; e += 512) {
        int h = e >> 7, rr = e & 127;
        float P = S[(O_SPC >> 2) + rr * 8 + h] + S[(O_SPC >> 2) + 1024 + rr * 8 + h];
        const float* st = S + (O_ST >> 2) + rr * 4;
        const float* sqp = S + (O_QS >> 2) + rr * 4;
        float su = (st[0] + st[1]) + (st[2] + st[3]);
        float sq = (sqp[0] + sqp[1]) + (sqp[2] + sqp[3]);
        float mu = su * (1.f / C_);
        float rs = rsqrtf(sq * (1.f / C_) - mu * mu + EPS);
        if (h == 0) { S[(O_MU >> 2) + rr] = mu; S[(O_RS >> 2) + rr] = rs; }
        S[(O_SC >> 2) + e] = (rs * (P - mu * S[(O_CG >> 2) + h]) + S[(O_CQC >> 2) + h])
                             * S[(O_IOR >> 2) + e];
    }
    __syncthreads();

    // ---- per-tile softmax; write w~ = e*rs as fp16; W, s2 per head ----
    if (wid < NH) {
        float v0 = S[(O_SC >> 2) + wid * 128 + lane];
        float v1 = S[(O_SC >> 2) + wid * 128 + 32 + lane];
        float v2 = S[(O_SC >> 2) + wid * 128 + 64 + lane];
        float v3 = S[(O_SC >> 2) + wid * 128 + 96 + lane];
        float mx = fmaxf(fmaxf(v0, v1), fmaxf(v2, v3));
        #pragma unroll
        for (int o = 16; o >= 1; o >>= 1) mx = fmaxf(mx, __shfl_xor_sync(~0u, mx, o));
        float e0 = __expf(v0 - mx), e1 = __expf(v1 - mx);
        float e2 = __expf(v2 - mx), e3 = __expf(v3 - mx);
        float rs0 = S[(O_RS >> 2) + lane],      mu0 = S[(O_MU >> 2) + lane];
        float rs1 = S[(O_RS >> 2) + 32 + lane], mu1 = S[(O_MU >> 2) + 32 + lane];
        float rs2 = S[(O_RS >> 2) + 64 + lane], mu2 = S[(O_MU >> 2) + 64 + lane];
        float rs3 = S[(O_RS >> 2) + 96 + lane], mu3 = S[(O_MU >> 2) + 96 + lane];
        float w0 = e0 * rs0, w1 = e1 * rs1, w2 = e2 * rs2, w3 = e3 * rs3;
        *(__half*)(sm + O_WH + (wid * 136 + lane) * 2) = __float2half_rn(w0);
        *(__half*)(sm + O_WH + (wid * 136 + 32 + lane) * 2) = __float2half_rn(w1);
        *(__half*)(sm + O_WH + (wid * 136 + 64 + lane) * 2) = __float2half_rn(w2);
        *(__half*)(sm + O_WH + (wid * 136 + 96 + lane) * 2) = __float2half_rn(w3);
        float es = (e0 + e1) + (e2 + e3);
        float s2 = w0 * mu0 + w1 * mu1 + w2 * mu2 + w3 * mu3;
        #pragma unroll
        for (int o = 16; o >= 1; o >>= 1) {
            es += __shfl_xor_sync(~0u, es, o);
            s2 += __shfl_xor_sync(~0u, s2, o);
        }
        if (lane == 0) {
            g_pmax[j * NH + wid] = mx;
            g_psum[j * NH + wid] = es;
            S[(O_CW >> 2) + wid] = es;
            S[(O_CS2 >> 2) + wid] = s2;
        }
    }
    __syncthreads();

    // ---- ctx MMA: ctxT[256,8] = msm^T @ w~^T; apply LN-fold; write pctx ----
    {
        const int ct = wid;                       // m-tile = 16 cols
        float dC[4] = {0.f, 0.f, 0.f, 0.f};
        uint32_t aA = smb + O_MSM + ((((lg >> 1) << 3) + lr) * 264 + ct * 16 + (lg & 1) * 8) * 2;
        uint32_t bA = smb + O_WH + ((lane & 7) * 136 + ((lane >> 3) & 1) * 8) * 2;
        #pragma unroll
        for (int kk = 0; kk < 8; kk++) {
            int r = kk * 16;
            uint32_t a[4], bb[2];
            ldmx4t(a, aA + r * 528);
            ldmx2(bb, bA + r * 2);
            mma16816(dC, a, bb[0], bb[1]);
        }
        int c = ct * 16 + (lane >> 2), h0 = (lane & 3) * 2;
        float g1 = S[(O_GIP >> 2) + c],     e1 = S[(O_BEI >> 2) + c];
        float g2 = S[(O_GIP >> 2) + c + 8], e2 = S[(O_BEI >> 2) + c + 8];
        float s20 = S[(O_CS2 >> 2) + h0], s21 = S[(O_CS2 >> 2) + h0 + 1];
        float W0 = S[(O_CW >> 2) + h0],  W1 = S[(O_CW >> 2) + h0 + 1];
        float* pc = g_pctx + (size_t)j * (NH * C_);
        pc[h0 * 256 + c]           = g1 * (dC[0] - s20) + e1 * W0;
        pc[(h0 + 1) * 256 + c]     = g1 * (dC[1] - s21) + e1 * W1;
        pc[h0 * 256 + c + 8]       = g2 * (dC[2] - s20) + e2 * W0;
        pc[(h0 + 1) * 256 + c + 8] = g2 * (dC[3] - s21) + e2 * W1;
    }
}

// ---- K2a: parallel softmax-combine of 128 partials, one block per (b,h) ----
__global__ void k2a() {
    __shared__ float pm[128], ps[128], ef[128], red[4], red2[4], cacc[4 * 256];
    const int b = blockIdx.x >> 3, h = blockIdx.x & 7;
    const int t = threadIdx.x, lane = t & 31;
    const int col = t & 255, sl = t >> 8;
    if (t < 128) {
        pm[t] = g_pmax[(b * 128 + t) * NH + h];
        ps[t] = g_psum[(b * 128 + t) * NH + h];
    }
    __syncthreads();
    if (t < 128) {
        float v = pm[t];
        #pragma unroll
        for (int o = 16; o >= 1; o >>= 1) v = fmaxf(v, __shfl_xor_sync(~0u, v, o));
        if (lane == 0) red[t >> 5] = v;
    }
    __syncthreads();
    float gmax = fmaxf(fmaxf(red[0], red[1]), fmaxf(red[2], red[3]));
    if (t < 128) ef[t] = __expf(pm[t] - gmax);
    __syncthreads();
    if (t < 128) {
        float v = ps[t] * ef[t];
        #pragma unroll
        for (int o = 16; o >= 1; o >>= 1) v += __shfl_xor_sync(~0u, v, o);
        if (lane == 0) red2[t >> 5] = v;
    }
    __syncthreads();
    float acc = 0.f;
    const float* p = g_pctx + ((size_t)(b * 128 + sl * 32) * NH + h) * C_ + col;
    #pragma unroll 4
    for (int ch = 0; ch < 32; ch++)
        acc += ef[sl * 32 + ch] * p[(size_t)ch * NH * C_];
    cacc[sl * 256 + col] = acc;
    __syncthreads();
    if (sl == 0) {
        float inv = 1.f / (red2[0] + red2[1] + red2[2] + red2[3]);
        float tot = cacc[col] + cacc[256 + col] + cacc[512 + col] + cacc[768 + col];
        g_ctxn[(b * NH + h) * C_ + col] = tot * inv;
    }
}

// ---- K2b: V-proj + residual + LN + FFN, 1024 threads with k-split ----
__global__ void __launch_bounds__(1024) k2b(
    const float* __restrict__ query, const float* __restrict__ W_kv,
    const float* __restrict__ b_kv, const float* __restrict__ g_f,
    const float* __restrict__ be_f, const float* __restrict__ W1,
    const float* __restrict__ b1, const float* __restrict__ W2,
    const float* __restrict__ b2, float* __restrict__ out) {
    __shared__ float ctxn[NH * C_], xs[C_], hs[C_], us[FFN], part[1024], red[8], red2[8];
    const int b = blockIdx.x, t = threadIdx.x, lane = t & 31, wid = t >> 5;
    for (int i = t; i < NH * C_; i += 1024) ctxn[i] = g_ctxn[b * NH * C_ + i];
    __syncthreads();
    {
        const int tt = t & 255, sl = t >> 8;
        const int h = tt >> 5;
        const float* W = W_kv + C_ + tt;
        const float* cx = ctxn + h * C_ + sl * 64;
        float a0 = 0.f, a1 = 0.f, a2 = 0.f, a3 = 0.f;
        #pragma unroll 4
        for (int c = 0; c < 64; c += 4) {
            a0 += cx[c] * W[(size_t)(sl * 64 + c) * (2 * C_)];
            a1 += cx[c + 1] * W[(size_t)(sl * 64 + c + 1) * (2 * C_)];
            a2 += cx[c + 2] * W[(size_t)(sl * 64 + c + 2) * (2 * C_)];
            a3 += cx[c + 3] * W[(size_t)(sl * 64 + c + 3) * (2 * C_)];
        }
        part[sl * 256 + tt] = (a0 + a1) + (a2 + a3);
    }
    __syncthreads();
    if (t < C_) {
        float x = b_kv[C_ + t] + ((part[t] + part[256 + t]) + (part[512 + t] + part[768 + t]))
                + query[b * C_ + t];
        xs[t] = x;
        float s = x, s2 = x * x;
        #pragma unroll
        for (int o = 16; o >= 1; o >>= 1) {
            s += __shfl_xor_sync(~0u, s, o);
            s2 += __shfl_xor_sync(~0u, s2, o);
        }
        if (lane == 0) { red[wid] = s; red2[wid] = s2; }
    }
    __syncthreads();
    if (t < C_) {
        float su = 0.f, sq = 0.f;
        #pragma unroll
        for (int i = 0; i < 8; i++) { su += red[i]; sq += red2[i]; }
        float mean = su / C_, var = sq / C_ - mean * mean, rs = rsqrtf(var + EPS);
        hs[t] = (xs[t] - mean) * rs * g_f[t] + be_f[t];
    }
    __syncthreads();
    {
        const int f = t & 511, sl = t >> 9;
        const float* W = W1 + f;
        const int c0 = sl * 128;
        float a0 = 0.f, a1 = 0.f, a2 = 0.f, a3 = 0.f;
        #pragma unroll 4
        for (int c = 0; c < 128; c += 4) {
            a0 += hs[c0 + c] * W[(size_t)(c0 + c) * FFN];
            a1 += hs[c0 + c + 1] * W[(size_t)(c0 + c + 1) * FFN];
            a2 += hs[c0 + c + 2] * W[(size_t)(c0 + c + 2) * FFN];
            a3 += hs[c0 + c + 3] * W[(size_t)(c0 + c + 3) * FFN];
        }
        part[sl * 512 + f] = (a0 + a1) + (a2 + a3);
    }
    __syncthreads();
    if (t < FFN) {
        float u = b1[t] + part[t] + part[512 + t];
        us[t] = 0.5f * u * (1.f + erff(u * 0.70710678118654752f));
    }
    __syncthreads();
    {
        const int tt = t & 255, sl = t >> 8;
        const float* W = W2 + tt;
        const int f0 = sl * 128;
        float a0 = 0.f, a1 = 0.f, a2 = 0.f, a3 = 0.f;
        #pragma unroll 4
        for (int f = 0; f < 128; f += 4) {
            a0 += us[f0 + f] * W[(size_t)(f0 + f) * C_];
            a1 += us[f0 + f + 1] * W[(size_t)(f0 + f + 1) * C_];
            a2 += us[f0 + f + 2] * W[(size_t)(f0 + f + 2) * C_];
            a3 += us[f0 + f + 3] * W[(size_t)(f0 + f + 3) * C_];
        }
        part[sl * 256 + tt] = (a0 + a1) + (a2 + a3);
    }
    __syncthreads();
    if (t < C_)
        out[b * C_ + t] = xs[t] + b2[t]
            + ((part[t] + part[256 + t]) + (part[512 + t] + part[768 + t]));
}

extern "C" void kernel_launch(void* const* d_in, const int* in_sizes, int n_in,
                              void* d_out, int out_size) {
    const float* query = (const float*)d_in[0];
    const float* mem   = (const float*)d_in[1];
    const float* ior   = (const float*)d_in[2];
    const float* W_ip  = (const float*)d_in[3];
    const float* b_ip  = (const float*)d_in[4];
    const float* g_ip  = (const float*)d_in[5];
    const float* be_ip = (const float*)d_in[6];
    const float* W_q   = (const float*)d_in[7];
    const float* b_q   = (const float*)d_in[8];
    const float* W_kv  = (const float*)d_in[9];
    const float* b_kv  = (const float*)d_in[10];
    const float* g_q   = (const float*)d_in[11];
    const float* be_q  = (const float*)d_in[12];
    const float* g_f   = (const float*)d_in[13];
    const float* be_f  = (const float*)d_in[14];
    const float* W1    = (const float*)d_in[15];
    const float* b1    = (const float*)d_in[16];
    const float* W2    = (const float*)d_in[17];
    const float* b2    = (const float*)d_in[18];

    cudaFuncSetAttribute(k1, cudaFuncAttributeMaxDynamicSharedMemorySize, SM1);
    k0b<<<dim3(8, 8), dim3(32, 32)>>>(W_ip);
    k0<<<B_, 1024>>>(query, W_q, b_q, W_kv, b_kv, g_q, be_q, g_ip, be_ip);
    kmid<<<1, 32>>>();
    k1<<<JOBS, 512, SM1>>>(mem, ior, b_ip, g_ip, be_ip);
    k2a<<<B_ * NH, 1024>>>();
    k2b<<<B_, 1024>>>(query, W_kv, b_kv, g_f, be_f, W1, b1, W2, b2, (float*)d_out);
}